// round 4
// baseline (speedup 1.0000x reference)
#include <cuda_runtime.h>
#include <cstdint>
#include <math.h>

#define NN 8192
#define DD 128
#define NE (NN*3)

// ---------------- device scratch (no allocations allowed) ----------------
__device__ float g_sq[NN];
__device__ unsigned long long g_cand[2ull*NN*16*3];
__device__ int g_nbr[NE];
__device__ float g_xp[(size_t)NN*256];    // x @ W, [N][H=2][128]
__device__ float g_as[NN*2];
__device__ float g_ad[NN*2];
__device__ float g_denom[NN*2];
__device__ float g_w[NE*2];
__device__ float g_acc[(size_t)NN*256];   // aggregated messages [N][H][128]

__device__ __forceinline__ unsigned encf(float f){
  unsigned u = __float_as_uint(f);
  return (u & 0x80000000u) ? ~u : (u | 0x80000000u);
}
__device__ __forceinline__ void ins3(unsigned long long k,
                                     unsigned long long &b0,
                                     unsigned long long &b1,
                                     unsigned long long &b2){
  if (k < b2){
    if (k < b1){
      b2 = b1;
      if (k < b0){ b1 = b0; b0 = k; } else { b1 = k; }
    } else { b2 = k; }
  }
}

// packed f32x2 FMA (Blackwell; ptxas never auto-emits)
__device__ __forceinline__ void ffma2(unsigned long long &d, unsigned long long a, unsigned long long b){
  asm("fma.rn.f32x2 %0, %1, %2, %0;" : "+l"(d) : "l"(a), "l"(b));
}
__device__ __forceinline__ float lo32(unsigned long long v){ return __uint_as_float((unsigned)v); }
__device__ __forceinline__ float hi32(unsigned long long v){ return __uint_as_float((unsigned)(v >> 32)); }

// ---------------- k1: row squared norms (warp per row) ----------------
__global__ void k_sqnorm(const float4* __restrict__ X4){
  int g = blockIdx.x*blockDim.x + threadIdx.x;
  int row = g >> 5, lane = g & 31;
  if (row >= NN) return;
  float4 v = X4[row*32 + lane];
  float s = v.x*v.x + v.y*v.y + v.z*v.z + v.w*v.w;
  #pragma unroll
  for (int o = 16; o; o >>= 1) s += __shfl_xor_sync(0xffffffffu, s, o);
  if (lane == 0) g_sq[row] = s;
}

// ---------------- k2: fused fp32 x@x^T + running top-3 (pre-packed FFMA2) ----------------
// grid 128 = 64 i-blocks x 2 j-splits, 512 threads.
// smem: A duplicated-pair layout aD[k][r]={v,v} (128KB, loaded once) +
//       B transposed sB[k][j] with 16B-chunk XOR swizzle (64KB, per tile).
// Per thread: 4 rows (4ty..) x 8 cols (8tx..), accs packed over col pairs.
// Inner loop per k: 4x LDS.128 (pre-packed operands) + 16 FFMA2. Zero MOVs.
__global__ __launch_bounds__(512, 1) void k_knn(const float* __restrict__ X){
  extern __shared__ float smem[];
  float* sA = smem;            // 32768 floats (128KB): word = k*256 + r*2
  float* sB = smem + 32768;    // 16384 floats (64KB):  word = k*128 + swz(j)
  const float4* X4 = (const float4*)X;
  int tid = threadIdx.x;
  int tx = tid & 15, ty = tid >> 4;          // tx 0..15 (cols), ty 0..31 (rows)
  int ib = blockIdx.x >> 1, split = blockIdx.x & 1;
  int i0 = ib*128;

  // ---- prologue: A-dup + B tile 0 ----
  #pragma unroll
  for (int l = 0; l < 8; l++){
    int idx = tid + l*512;
    int r = idx & 127, k4 = idx >> 7;        // k4 0..31
    float4 v = X4[(size_t)(i0 + r)*32 + k4];
    float* p = sA + (k4*4)*256 + r*2;
    p[0]   = v.x; p[1]   = v.x;
    p[256] = v.y; p[257] = v.y;
    p[512] = v.z; p[513] = v.z;
    p[768] = v.w; p[769] = v.w;
  }
  {
    int j0 = split*4096;
    #pragma unroll
    for (int l = 0; l < 8; l++){
      int idx = tid + l*512;
      int j = idx & 127, k4 = idx >> 7;
      float4 v = X4[(size_t)(j0 + j)*32 + k4];
      int cj = j >> 2;
      int sw = ((cj ^ (cj >> 3)) << 2) | (j & 3);
      float* p = sB + (k4*4)*128 + sw;
      p[0]   = v.x;
      p[128] = v.y;
      p[256] = v.z;
      p[384] = v.w;
    }
  }
  __syncthreads();

  float sqi[4];
  #pragma unroll
  for (int m = 0; m < 4; m++) sqi[m] = g_sq[i0 + ty*4 + m];

  unsigned long long best[4][3];
  #pragma unroll
  for (int m = 0; m < 4; m++){ best[m][0] = ~0ull; best[m][1] = ~0ull; best[m][2] = ~0ull; }

  // swizzled read word-offsets for this thread's two 16B B chunks
  int c0 = 2*tx, c1 = 2*tx + 1;
  int ob0 = (c0 ^ (c0 >> 3)) << 2;
  int ob1 = (c1 ^ (c1 >> 3)) << 2;
  int oa  = 8*ty;

  for (int jt = 0; jt < 32; jt++){
    int j0c = split*4096 + jt*128;

    // register prefetch of next B tile (overlaps with compute)
    float4 pf[8];
    if (jt < 31){
      int j0n = j0c + 128;
      #pragma unroll
      for (int l = 0; l < 8; l++){
        int idx = tid + l*512;
        int j = idx & 127, k4 = idx >> 7;
        pf[l] = X4[(size_t)(j0n + j)*32 + k4];
      }
    }

    unsigned long long acc[4][4];
    #pragma unroll
    for (int a = 0; a < 4; a++)
      #pragma unroll
      for (int b = 0; b < 4; b++) acc[a][b] = 0ull;

    #pragma unroll 8
    for (int k = 0; k < 128; k++){
      ulonglong2 a01 = *(const ulonglong2*)(sA + k*256 + oa);
      ulonglong2 a23 = *(const ulonglong2*)(sA + k*256 + oa + 4);
      ulonglong2 b03 = *(const ulonglong2*)(sB + k*128 + ob0);
      ulonglong2 b47 = *(const ulonglong2*)(sB + k*128 + ob1);
      ffma2(acc[0][0], a01.x, b03.x); ffma2(acc[0][1], a01.x, b03.y);
      ffma2(acc[0][2], a01.x, b47.x); ffma2(acc[0][3], a01.x, b47.y);
      ffma2(acc[1][0], a01.y, b03.x); ffma2(acc[1][1], a01.y, b03.y);
      ffma2(acc[1][2], a01.y, b47.x); ffma2(acc[1][3], a01.y, b47.y);
      ffma2(acc[2][0], a23.x, b03.x); ffma2(acc[2][1], a23.x, b03.y);
      ffma2(acc[2][2], a23.x, b47.x); ffma2(acc[2][3], a23.x, b47.y);
      ffma2(acc[3][0], a23.y, b03.x); ffma2(acc[3][1], a23.y, b03.y);
      ffma2(acc[3][2], a23.y, b47.x); ffma2(acc[3][3], a23.y, b47.y);
    }

    // epilogue: d2 = (sq_i + sq_j) - 2*dot ; running top-3
    #pragma unroll
    for (int jp = 0; jp < 4; jp++){
      int col0 = 8*tx + 2*jp;
      float sq0 = __ldg(&g_sq[j0c + col0]);
      float sq1 = __ldg(&g_sq[j0c + col0 + 1]);
      #pragma unroll
      for (int mi = 0; mi < 4; mi++){
        float f0 = lo32(acc[mi][jp]);
        float f1 = hi32(acc[mi][jp]);
        float d2a = (sqi[mi] + sq0) - 2.0f*f0;
        float d2b = (sqi[mi] + sq1) - 2.0f*f1;
        unsigned long long ka = ((unsigned long long)encf(d2a) << 32) | (unsigned)(j0c + col0);
        unsigned long long kb = ((unsigned long long)encf(d2b) << 32) | (unsigned)(j0c + col0 + 1);
        ins3(ka, best[mi][0], best[mi][1], best[mi][2]);
        ins3(kb, best[mi][0], best[mi][1], best[mi][2]);
      }
    }

    if (jt < 31){
      __syncthreads();           // everyone done reading sB
      #pragma unroll
      for (int l = 0; l < 8; l++){
        int idx = tid + l*512;
        int j = idx & 127, k4 = idx >> 7;
        int cj = j >> 2;
        int sw = ((cj ^ (cj >> 3)) << 2) | (j & 3);
        float* p = sB + (k4*4)*128 + sw;
        p[0]   = pf[l].x;
        p[128] = pf[l].y;
        p[256] = pf[l].z;
        p[384] = pf[l].w;
      }
      __syncthreads();           // new tile visible
    }
  }

  #pragma unroll
  for (int m = 0; m < 4; m++){
    int row = i0 + ty*4 + m;
    size_t base = ((size_t)(split*NN + row)*16 + tx)*3;
    g_cand[base+0] = best[m][0];
    g_cand[base+1] = best[m][1];
    g_cand[base+2] = best[m][2];
  }
}

// ---------------- k3: merge partial top-3 (warp per row) ----------------
__global__ void k_merge(){
  int g = blockIdx.x*blockDim.x + threadIdx.x;
  int row = g >> 5, lane = g & 31;
  if (row >= NN) return;
  int split = lane >> 4, tx = lane & 15;
  size_t base = ((size_t)(split*NN + row)*16 + tx)*3;
  unsigned long long b0 = g_cand[base+0];
  unsigned long long b1 = g_cand[base+1];
  unsigned long long b2 = g_cand[base+2];
  #pragma unroll
  for (int o = 16; o; o >>= 1){
    unsigned long long c0 = __shfl_xor_sync(0xffffffffu, b0, o);
    unsigned long long c1 = __shfl_xor_sync(0xffffffffu, b1, o);
    unsigned long long c2 = __shfl_xor_sync(0xffffffffu, b2, o);
    ins3(c0, b0, b1, b2);
    ins3(c1, b0, b1, b2);
    ins3(c2, b0, b1, b2);
  }
  if (lane == 0){
    g_nbr[row*3+0] = (int)(b0 & 0xffffffffull);
    g_nbr[row*3+1] = (int)(b1 & 0xffffffffull);
    g_nbr[row*3+2] = (int)(b2 & 0xffffffffull);
  }
}

// ---------------- k4: xp = x @ W (grid 128 = 64 ib x 2 heads) ----------------
__global__ __launch_bounds__(256) void k_xp(const float* __restrict__ X,
                                            const float* __restrict__ W){
  __shared__ float sA[32*129];
  __shared__ float sW[32*129];
  const float4* X4 = (const float4*)X;
  const float4* W4 = (const float4*)W;
  int tid = threadIdx.x;
  int tx = tid & 15, ty = tid >> 4;
  int ib = blockIdx.x >> 1, h = blockIdx.x & 1;
  int i0 = ib*128;
  float acc[8][8];
  #pragma unroll
  for (int a = 0; a < 8; a++)
    #pragma unroll
    for (int b = 0; b < 8; b++) acc[a][b] = 0.f;

  for (int kc = 0; kc < 4; kc++){
    __syncthreads();
    #pragma unroll
    for (int l = 0; l < 4; l++){
      int idx = tid + l*256;
      int r = idx >> 3, k4 = idx & 7;
      float4 va = X4[(i0 + r)*32 + kc*8 + k4];
      sA[(k4*4+0)*129 + r] = va.x;
      sA[(k4*4+1)*129 + r] = va.y;
      sA[(k4*4+2)*129 + r] = va.z;
      sA[(k4*4+3)*129 + r] = va.w;
      int dd = idx >> 5, c4 = idx & 31;
      float4 vw = W4[(size_t)(kc*32 + dd)*64 + h*32 + c4];
      sW[dd*129 + c4*4 + 0] = vw.x;
      sW[dd*129 + c4*4 + 1] = vw.y;
      sW[dd*129 + c4*4 + 2] = vw.z;
      sW[dd*129 + c4*4 + 3] = vw.w;
    }
    __syncthreads();
    #pragma unroll 4
    for (int k = 0; k < 32; k++){
      float a[8], b[8];
      #pragma unroll
      for (int m = 0; m < 8; m++) a[m] = sA[k*129 + ty + 16*m];
      #pragma unroll
      for (int m = 0; m < 8; m++) b[m] = sW[k*129 + tx + 16*m];
      #pragma unroll
      for (int mi = 0; mi < 8; mi++)
        #pragma unroll
        for (int mj = 0; mj < 8; mj++)
          acc[mi][mj] = fmaf(a[mi], b[mj], acc[mi][mj]);
    }
  }
  #pragma unroll
  for (int mi = 0; mi < 8; mi++)
    #pragma unroll
    for (int mj = 0; mj < 8; mj++)
      g_xp[(size_t)(i0 + ty + 16*mi)*256 + h*128 + tx + 16*mj] = acc[mi][mj];
}

// ---------------- k5: attention coeffs + init denom/acc ----------------
__global__ void k_attn(const float* __restrict__ att_src,
                       const float* __restrict__ att_dst){
  int g = blockIdx.x*blockDim.x + threadIdx.x;
  int n = g >> 5, lane = g & 31;
  if (n >= NN) return;
  const float4* xp4 = (const float4*)g_xp;
  float4 x0 = xp4[(size_t)n*64 + lane];
  float4 x1 = xp4[(size_t)n*64 + 32 + lane];
  const float4* s4 = (const float4*)att_src;
  const float4* d4 = (const float4*)att_dst;
  float4 a0 = s4[lane], a1 = s4[32 + lane];
  float4 c0 = d4[lane], c1 = d4[32 + lane];
  float vs0 = x0.x*a0.x + x0.y*a0.y + x0.z*a0.z + x0.w*a0.w;
  float vs1 = x1.x*a1.x + x1.y*a1.y + x1.z*a1.z + x1.w*a1.w;
  float vd0 = x0.x*c0.x + x0.y*c0.y + x0.z*c0.z + x0.w*c0.w;
  float vd1 = x1.x*c1.x + x1.y*c1.y + x1.z*c1.z + x1.w*c1.w;
  #pragma unroll
  for (int o = 16; o; o >>= 1){
    vs0 += __shfl_xor_sync(0xffffffffu, vs0, o);
    vs1 += __shfl_xor_sync(0xffffffffu, vs1, o);
    vd0 += __shfl_xor_sync(0xffffffffu, vd0, o);
    vd1 += __shfl_xor_sync(0xffffffffu, vd1, o);
  }
  if (lane == 0){
    g_as[n*2+0] = vs0; g_as[n*2+1] = vs1;
    g_ad[n*2+0] = vd0; g_ad[n*2+1] = vd1;
    g_denom[n*2+0] = 0.f; g_denom[n*2+1] = 0.f;
  }
  float4 z = make_float4(0.f, 0.f, 0.f, 0.f);
  ((float4*)g_acc)[(size_t)n*64 + lane] = z;
  ((float4*)g_acc)[(size_t)n*64 + 32 + lane] = z;
}

// ---------------- k6: exp + segment sum (no max-shift: |e| small, fp32-safe) ----------------
__global__ void k_esum(){
  int idx = blockIdx.x*blockDim.x + threadIdx.x;
  if (idx >= NE*2) return;
  int e = idx >> 1, h = idx & 1;
  int s = e/3;
  int d = g_nbr[e];
  float v = g_as[s*2+h] + g_ad[d*2+h];
  v = v > 0.f ? v : 0.2f*v;
  float w = __expf(v);
  g_w[idx] = w;
  atomicAdd(&g_denom[d*2+h], w);
}

// ---------------- k7: aggregate messages (warp per edge-head) ----------------
__global__ void k_agg(){
  int g = blockIdx.x*blockDim.x + threadIdx.x;
  int eh = g >> 5, lane = g & 31;
  if (eh >= NE*2) return;
  int e = eh >> 1, h = eh & 1;
  int s = e/3;
  int d = g_nbr[e];
  float alpha = g_w[eh] / g_denom[d*2+h];
  const float4* xp4 = (const float4*)g_xp;
  float4 v = xp4[(size_t)s*64 + h*32 + lane];
  float* dst = &g_acc[(size_t)d*256 + h*128 + lane*4];
  atomicAdd(dst+0, alpha*v.x);
  atomicAdd(dst+1, alpha*v.y);
  atomicAdd(dst+2, alpha*v.z);
  atomicAdd(dst+3, alpha*v.w);
}

// ---------------- k8: head-mean + bias + LayerNorm + ReLU + residual ----------------
__global__ void k_final(const float* __restrict__ X,
                        const float* __restrict__ bias,
                        const float* __restrict__ gamma,
                        const float* __restrict__ beta,
                        float* __restrict__ out){
  int g = blockIdx.x*blockDim.x + threadIdx.x;
  int n = g >> 5, lane = g & 31;
  if (n >= NN) return;
  float v[4];
  #pragma unroll
  for (int c = 0; c < 4; c++){
    int dd = lane*4 + c;
    float a0 = g_acc[(size_t)n*256 + dd];
    float a1 = g_acc[(size_t)n*256 + 128 + dd];
    v[c] = 0.5f*(a0 + a1) + bias[dd];
  }
  float s = v[0]+v[1]+v[2]+v[3];
  #pragma unroll
  for (int o = 16; o; o >>= 1) s += __shfl_xor_sync(0xffffffffu, s, o);
  float mu = s * (1.0f/128.0f);
  float q = 0.f;
  #pragma unroll
  for (int c = 0; c < 4; c++){ float t = v[c]-mu; q += t*t; }
  #pragma unroll
  for (int o = 16; o; o >>= 1) q += __shfl_xor_sync(0xffffffffu, q, o);
  float rstd = rsqrtf(q*(1.0f/128.0f) + 1e-5f);
  #pragma unroll
  for (int c = 0; c < 4; c++){
    int dd = lane*4 + c;
    float y = (v[c]-mu)*rstd*gamma[dd] + beta[dd];
    y = y > 0.f ? y : 0.f;
    out[(size_t)n*128 + dd] = X[(size_t)n*128 + dd] + y;
  }
}

// ---------------- launch ----------------
extern "C" void kernel_launch(void* const* d_in, const int* in_sizes, int n_in,
                              void* d_out, int out_size) {
  const float* prototypes = (const float*)d_in[0];
  // d_in[1] = labels (unused in forward)
  const float* W       = (const float*)d_in[2];
  const float* att_src = (const float*)d_in[3];
  const float* att_dst = (const float*)d_in[4];
  const float* bias    = (const float*)d_in[5];
  const float* gamma   = (const float*)d_in[6];
  const float* beta    = (const float*)d_in[7];
  float* out = (float*)d_out;

  const int KNN_SMEM = (32768 + 16384) * 4;   // 192 KB dynamic smem
  cudaFuncSetAttribute(k_knn, cudaFuncAttributeMaxDynamicSharedMemorySize, KNN_SMEM);

  k_sqnorm<<<NN/8, 256>>>((const float4*)prototypes);
  k_knn<<<128, 512, KNN_SMEM>>>(prototypes);
  k_merge<<<NN/8, 256>>>();
  k_xp<<<128, 256>>>(prototypes, W);
  k_attn<<<NN/8, 256>>>(att_src, att_dst);
  k_esum<<<(NE*2+255)/256, 256>>>();
  k_agg<<<(NE*2*32+255)/256, 256>>>();
  k_final<<<NN/8, 256>>>(prototypes, bias, gamma, beta, out);
}

// round 7
// speedup vs baseline: 2.3619x; 2.3619x over previous
#include <cuda_runtime.h>
#include <cuda_bf16.h>
#include <cstdint>
#include <math.h>

#define NN 8192
#define DD 128
#define NE (NN*3)

// ---------------- device scratch (no allocations allowed) ----------------
__device__ float g_sq[NN];
__device__ __nv_bfloat16 g_xbf[(size_t)NN*DD];
__device__ unsigned long long g_cand[2ull*NN*16];   // [split][row][16] approx top keys
__device__ int g_nbr[NE];
__device__ float g_xp[(size_t)NN*256];    // x @ W, [N][H=2][128]
__device__ float g_as[NN*2];
__device__ float g_ad[NN*2];
__device__ float g_denom[NN*2];
__device__ float g_w[NE*2];
__device__ float g_acc[(size_t)NN*256];   // aggregated messages [N][H][128]

__device__ __forceinline__ unsigned encf(float f){
  unsigned u = __float_as_uint(f);
  return (u & 0x80000000u) ? ~u : (u | 0x80000000u);
}
__device__ __forceinline__ void ins3(unsigned long long k,
                                     unsigned long long &b0,
                                     unsigned long long &b1,
                                     unsigned long long &b2){
  if (k < b2){
    if (k < b1){
      b2 = b1;
      if (k < b0){ b1 = b0; b0 = k; } else { b1 = k; }
    } else { b2 = k; }
  }
}
// insert if smaller than current 4th-best (caller pre-guards with key < b[3])
__device__ __forceinline__ void ins4(unsigned long long k, unsigned long long* b){
  b[3] = k;
  #pragma unroll
  for (int s = 3; s > 0; s--){
    if (b[s] < b[s-1]){ unsigned long long t = b[s]; b[s] = b[s-1]; b[s-1] = t; }
  }
}

__device__ __forceinline__ uint32_t smem_u32(const void* p){
  uint32_t a;
  asm("{ .reg .u64 t; cvta.to.shared.u64 t, %1; cvt.u32.u64 %0, t; }" : "=r"(a) : "l"(p));
  return a;
}
__device__ __forceinline__ void ldsm4(uint32_t &r0, uint32_t &r1, uint32_t &r2, uint32_t &r3, uint32_t a){
  asm volatile("ldmatrix.sync.aligned.m8n8.x4.shared.b16 {%0,%1,%2,%3}, [%4];"
    : "=r"(r0), "=r"(r1), "=r"(r2), "=r"(r3) : "r"(a));
}
__device__ __forceinline__ void mma16816(float* d, const uint32_t* a, uint32_t b0, uint32_t b1){
  asm volatile("mma.sync.aligned.m16n8k16.row.col.f32.bf16.bf16.f32 "
    "{%0,%1,%2,%3}, {%4,%5,%6,%7}, {%8,%9}, {%0,%1,%2,%3};"
    : "+f"(d[0]), "+f"(d[1]), "+f"(d[2]), "+f"(d[3])
    : "r"(a[0]), "r"(a[1]), "r"(a[2]), "r"(a[3]), "r"(b0), "r"(b1));
}

// ---------------- k1: row squared norms (warp per row) ----------------
__global__ void k_sqnorm(const float4* __restrict__ X4){
  int g = blockIdx.x*blockDim.x + threadIdx.x;
  int row = g >> 5, lane = g & 31;
  if (row >= NN) return;
  float4 v = X4[row*32 + lane];
  float s = v.x*v.x + v.y*v.y + v.z*v.z + v.w*v.w;
  #pragma unroll
  for (int o = 16; o; o >>= 1) s += __shfl_xor_sync(0xffffffffu, s, o);
  if (lane == 0) g_sq[row] = s;
}

// ---------------- k2: fp32 -> bf16 ----------------
__global__ void k_tobf16(const float* __restrict__ X){
  int i = blockIdx.x*blockDim.x + threadIdx.x;
  float2 v = ((const float2*)X)[i];
  __nv_bfloat162 b;
  b.x = __float2bfloat16(v.x);
  b.y = __float2bfloat16(v.y);
  ((__nv_bfloat162*)g_xbf)[i] = b;
}

// ---------------- k3: bf16 mma.sync filter: approx d2 top-4/(row,quarter,split) ----
// grid 128 = 64 i-tiles x 2 j-splits, 256 thr (8 warps, 16 rows/warp).
// smem rows pitch 272B (17 x 16B chunks) -> ldmatrix conflict-free, no swizzle.
static constexpr int PITCH  = 272;
static constexpr int SM_A   = 0;                    // 128*272 = 34816
static constexpr int SM_B0  = 34816;
static constexpr int SM_B1  = 69632;
static constexpr int SM_SQ0 = 104448;               // 512
static constexpr int SM_SQ1 = 104960;               // 512
static constexpr int SM_TOT = 105472;

__global__ __launch_bounds__(256, 1) void k_filter(){
  extern __shared__ char smem[];
  uint32_t sbase = smem_u32(smem);
  int tid = threadIdx.x;
  int w = tid >> 5, lane = tid & 31;
  int ib = blockIdx.x >> 1, split = blockIdx.x & 1;
  int i0 = ib*128;

  // load A tile (rows i0..i0+127): thread handles 8 chunks
  #pragma unroll
  for (int l = 0; l < 8; l++){
    int idx = tid + l*256;
    int r = idx >> 4, c = idx & 15;
    uint4 v = ((const uint4*)(g_xbf + (size_t)(i0 + r)*128))[c];
    *(uint4*)(smem + SM_A + r*PITCH + c*16) = v;
  }
  // load B tile 0 + sq0
  {
    int j0 = split*4096;
    #pragma unroll
    for (int l = 0; l < 8; l++){
      int idx = tid + l*256;
      int r = idx >> 4, c = idx & 15;
      uint4 v = ((const uint4*)(g_xbf + (size_t)(j0 + r)*128))[c];
      *(uint4*)(smem + SM_B0 + r*PITCH + c*16) = v;
    }
    if (tid < 128) ((float*)(smem + SM_SQ0))[tid] = g_sq[j0 + tid];
  }
  __syncthreads();

  // ldmatrix lane address components
  // A frag (x4): m0=r0-7/k0-7, m1=r8-15/k0-7, m2=r0-7/k8-15, m3=r8-15/k8-15
  uint32_t aAddr = sbase + SM_A
                 + (uint32_t)(16*w + (lane & 7) + 8*((lane >> 3) & 1))*PITCH
                 + (uint32_t)(((lane >> 4) & 1) << 4);
  // B frag (x4): m0=n0-7/k0-7, m1=n0-7/k8-15, m2=n8-15/k0-7, m3=n8-15/k8-15
  uint32_t bRowOff = (uint32_t)((lane & 7) + 8*((lane >> 4) & 1))*PITCH
                   + (uint32_t)(((lane >> 3) & 1) << 4);

  unsigned long long bu[4], bl[4];
  #pragma unroll
  for (int s = 0; s < 4; s++){ bu[s] = ~0ull; bl[s] = ~0ull; }

  int q = lane & 3;           // column quarter
  int rsub = lane >> 2;       // 0..7

  for (int t = 0; t < 32; t++){
    int j0 = split*4096 + t*128;
    uint32_t bBase = sbase + ((t & 1) ? SM_B1 : SM_B0);
    const float* sq = (const float*)(smem + ((t & 1) ? SM_SQ1 : SM_SQ0));

    // prefetch next B tile into regs
    uint4 pf[8]; float sqv = 0.f;
    if (t < 31){
      int j0n = j0 + 128;
      #pragma unroll
      for (int l = 0; l < 8; l++){
        int idx = tid + l*256;
        int r = idx >> 4, c = idx & 15;
        pf[l] = ((const uint4*)(g_xbf + (size_t)(j0n + r)*128))[c];
      }
      if (tid < 128) sqv = g_sq[j0n + tid];
    }

    float acc[16][4];
    #pragma unroll
    for (int a = 0; a < 16; a++)
      #pragma unroll
      for (int b = 0; b < 4; b++) acc[a][b] = 0.f;

    #pragma unroll
    for (int ks = 0; ks < 8; ks++){
      uint32_t A[4];
      ldsm4(A[0], A[1], A[2], A[3], aAddr + ks*32);
      #pragma unroll
      for (int p = 0; p < 8; p++){
        uint32_t b0, b1, b2, b3;
        ldsm4(b0, b1, b2, b3, bBase + bRowOff + (uint32_t)(p*16)*PITCH + ks*32);
        mma16816(acc[2*p],   A, b0, b1);
        mma16816(acc[2*p+1], A, b2, b3);
      }
    }

    // epilogue: approx d2 = sq_j - 2*dot; encoded-key top-4 (sentinel-safe)
    #pragma unroll
    for (int tt = 0; tt < 16; tt++){
      int c0 = tt*8 + 2*q;
      float sq0 = sq[c0], sq1 = sq[c0 + 1];
      unsigned long long k0u = ((unsigned long long)encf(sq0 - 2.0f*acc[tt][0]) << 32) | (unsigned)(j0 + c0);
      unsigned long long k1u = ((unsigned long long)encf(sq1 - 2.0f*acc[tt][1]) << 32) | (unsigned)(j0 + c0 + 1);
      unsigned long long k0l = ((unsigned long long)encf(sq0 - 2.0f*acc[tt][2]) << 32) | (unsigned)(j0 + c0);
      unsigned long long k1l = ((unsigned long long)encf(sq1 - 2.0f*acc[tt][3]) << 32) | (unsigned)(j0 + c0 + 1);
      if (k0u < bu[3]) ins4(k0u, bu);
      if (k1u < bu[3]) ins4(k1u, bu);
      if (k0l < bl[3]) ins4(k0l, bl);
      if (k1l < bl[3]) ins4(k1l, bl);
    }

    // store prefetched B into alternate buffer
    if (t < 31){
      char* nb = smem + (((t + 1) & 1) ? SM_B1 : SM_B0);
      #pragma unroll
      for (int l = 0; l < 8; l++){
        int idx = tid + l*256;
        int r = idx >> 4, c = idx & 15;
        *(uint4*)(nb + r*PITCH + c*16) = pf[l];
      }
      if (tid < 128) ((float*)(smem + (((t + 1) & 1) ? SM_SQ1 : SM_SQ0)))[tid] = sqv;
    }
    __syncthreads();
  }

  // write per-(row, quarter) top-4: rows 16w + rsub and +8
  int rowU = i0 + 16*w + rsub;
  int rowL = rowU + 8;
  size_t baseU = ((size_t)split*NN + rowU)*16 + q*4;
  size_t baseL = ((size_t)split*NN + rowL)*16 + q*4;
  #pragma unroll
  for (int s = 0; s < 4; s++){
    g_cand[baseU + s] = bu[s];
    g_cand[baseL + s] = bl[s];
  }
}

// ---------------- k4: exact fp32 rescore of 32 candidates -> top-3 ----------------
__global__ void k_rescore(const float* __restrict__ X){
  int g = blockIdx.x*blockDim.x + threadIdx.x;
  int row = g >> 5, lane = g & 31;
  if (row >= NN) return;
  int split = lane >> 4;
  unsigned long long ck = g_cand[((size_t)split*NN + row)*16 + (lane & 15)];
  int j = (int)(ck & 0xffffffffull) & (NN - 1);   // defensive clamp
  const float4* xi = (const float4*)(X + (size_t)row*128);
  const float4* xj = (const float4*)(X + (size_t)j*128);
  float dot = 0.f;
  #pragma unroll
  for (int k = 0; k < 32; k++){
    float4 a = xi[k], b = xj[k];
    dot = fmaf(a.x, b.x, dot); dot = fmaf(a.y, b.y, dot);
    dot = fmaf(a.z, b.z, dot); dot = fmaf(a.w, b.w, dot);
  }
  float d2 = (g_sq[row] + g_sq[j]) - 2.0f*dot;
  unsigned long long b0 = ((unsigned long long)encf(d2) << 32) | (unsigned)j;
  unsigned long long b1 = ~0ull, b2 = ~0ull;
  #pragma unroll
  for (int o = 16; o; o >>= 1){
    unsigned long long c0 = __shfl_xor_sync(0xffffffffu, b0, o);
    unsigned long long c1 = __shfl_xor_sync(0xffffffffu, b1, o);
    unsigned long long c2 = __shfl_xor_sync(0xffffffffu, b2, o);
    ins3(c0, b0, b1, b2);
    ins3(c1, b0, b1, b2);
    ins3(c2, b0, b1, b2);
  }
  if (lane == 0){
    g_nbr[row*3+0] = (int)(b0 & 0xffffffffull);
    g_nbr[row*3+1] = (int)(b1 & 0xffffffffull);
    g_nbr[row*3+2] = (int)(b2 & 0xffffffffull);
  }
}

// ---------------- k5: xp = x @ W (grid 128 = 64 ib x 2 heads) ----------------
__global__ __launch_bounds__(256) void k_xp(const float* __restrict__ X,
                                            const float* __restrict__ W){
  __shared__ float sA[32*129];
  __shared__ float sW[32*129];
  const float4* X4 = (const float4*)X;
  const float4* W4 = (const float4*)W;
  int tid = threadIdx.x;
  int tx = tid & 15, ty = tid >> 4;
  int ib = blockIdx.x >> 1, h = blockIdx.x & 1;
  int i0 = ib*128;
  float acc[8][8];
  #pragma unroll
  for (int a = 0; a < 8; a++)
    #pragma unroll
    for (int b = 0; b < 8; b++) acc[a][b] = 0.f;

  for (int kc = 0; kc < 4; kc++){
    __syncthreads();
    #pragma unroll
    for (int l = 0; l < 4; l++){
      int idx = tid + l*256;
      int r = idx >> 3, k4 = idx & 7;
      float4 va = X4[(i0 + r)*32 + kc*8 + k4];
      sA[(k4*4+0)*129 + r] = va.x;
      sA[(k4*4+1)*129 + r] = va.y;
      sA[(k4*4+2)*129 + r] = va.z;
      sA[(k4*4+3)*129 + r] = va.w;
      int dd = idx >> 5, c4 = idx & 31;
      float4 vw = W4[(size_t)(kc*32 + dd)*64 + h*32 + c4];
      sW[dd*129 + c4*4 + 0] = vw.x;
      sW[dd*129 + c4*4 + 1] = vw.y;
      sW[dd*129 + c4*4 + 2] = vw.z;
      sW[dd*129 + c4*4 + 3] = vw.w;
    }
    __syncthreads();
    #pragma unroll 4
    for (int k = 0; k < 32; k++){
      float a[8], b[8];
      #pragma unroll
      for (int m = 0; m < 8; m++) a[m] = sA[k*129 + ty + 16*m];
      #pragma unroll
      for (int m = 0; m < 8; m++) b[m] = sW[k*129 + tx + 16*m];
      #pragma unroll
      for (int mi = 0; mi < 8; mi++)
        #pragma unroll
        for (int mj = 0; mj < 8; mj++)
          acc[mi][mj] = fmaf(a[mi], b[mj], acc[mi][mj]);
    }
  }
  #pragma unroll
  for (int mi = 0; mi < 8; mi++)
    #pragma unroll
    for (int mj = 0; mj < 8; mj++)
      g_xp[(size_t)(i0 + ty + 16*mi)*256 + h*128 + tx + 16*mj] = acc[mi][mj];
}

// ---------------- k6: attention coeffs + init denom/acc ----------------
__global__ void k_attn(const float* __restrict__ att_src,
                       const float* __restrict__ att_dst){
  int g = blockIdx.x*blockDim.x + threadIdx.x;
  int n = g >> 5, lane = g & 31;
  if (n >= NN) return;
  const float4* xp4 = (const float4*)g_xp;
  float4 x0 = xp4[(size_t)n*64 + lane];
  float4 x1 = xp4[(size_t)n*64 + 32 + lane];
  const float4* s4 = (const float4*)att_src;
  const float4* d4 = (const float4*)att_dst;
  float4 a0 = s4[lane], a1 = s4[32 + lane];
  float4 c0 = d4[lane], c1 = d4[32 + lane];
  float vs0 = x0.x*a0.x + x0.y*a0.y + x0.z*a0.z + x0.w*a0.w;
  float vs1 = x1.x*a1.x + x1.y*a1.y + x1.z*a1.z + x1.w*a1.w;
  float vd0 = x0.x*c0.x + x0.y*c0.y + x0.z*c0.z + x0.w*c0.w;
  float vd1 = x1.x*c1.x + x1.y*c1.y + x1.z*c1.z + x1.w*c1.w;
  #pragma unroll
  for (int o = 16; o; o >>= 1){
    vs0 += __shfl_xor_sync(0xffffffffu, vs0, o);
    vs1 += __shfl_xor_sync(0xffffffffu, vs1, o);
    vd0 += __shfl_xor_sync(0xffffffffu, vd0, o);
    vd1 += __shfl_xor_sync(0xffffffffu, vd1, o);
  }
  if (lane == 0){
    g_as[n*2+0] = vs0; g_as[n*2+1] = vs1;
    g_ad[n*2+0] = vd0; g_ad[n*2+1] = vd1;
    g_denom[n*2+0] = 0.f; g_denom[n*2+1] = 0.f;
  }
  float4 z = make_float4(0.f, 0.f, 0.f, 0.f);
  ((float4*)g_acc)[(size_t)n*64 + lane] = z;
  ((float4*)g_acc)[(size_t)n*64 + 32 + lane] = z;
}

// ---------------- k7: exp + segment sum (no max-shift: |e| small, fp32-safe) -------
__global__ void k_esum(){
  int idx = blockIdx.x*blockDim.x + threadIdx.x;
  if (idx >= NE*2) return;
  int e = idx >> 1, h = idx & 1;
  int s = e/3;
  int d = g_nbr[e];
  float v = g_as[s*2+h] + g_ad[d*2+h];
  v = v > 0.f ? v : 0.2f*v;
  float w = __expf(v);
  g_w[idx] = w;
  atomicAdd(&g_denom[d*2+h], w);
}

// ---------------- k8: aggregate messages (warp per edge-head) ----------------
__global__ void k_agg(){
  int g = blockIdx.x*blockDim.x + threadIdx.x;
  int eh = g >> 5, lane = g & 31;
  if (eh >= NE*2) return;
  int e = eh >> 1, h = eh & 1;
  int s = e/3;
  int d = g_nbr[e];
  float alpha = g_w[eh] / g_denom[d*2+h];
  const float4* xp4 = (const float4*)g_xp;
  float4 v = xp4[(size_t)s*64 + h*32 + lane];
  float* dst = &g_acc[(size_t)d*256 + h*128 + lane*4];
  atomicAdd(dst+0, alpha*v.x);
  atomicAdd(dst+1, alpha*v.y);
  atomicAdd(dst+2, alpha*v.z);
  atomicAdd(dst+3, alpha*v.w);
}

// ---------------- k9: head-mean + bias + LayerNorm + ReLU + residual ----------------
__global__ void k_final(const float* __restrict__ X,
                        const float* __restrict__ bias,
                        const float* __restrict__ gamma,
                        const float* __restrict__ beta,
                        float* __restrict__ out){
  int g = blockIdx.x*blockDim.x + threadIdx.x;
  int n = g >> 5, lane = g & 31;
  if (n >= NN) return;
  float v[4];
  #pragma unroll
  for (int c = 0; c < 4; c++){
    int dd = lane*4 + c;
    float a0 = g_acc[(size_t)n*256 + dd];
    float a1 = g_acc[(size_t)n*256 + 128 + dd];
    v[c] = 0.5f*(a0 + a1) + bias[dd];
  }
  float s = v[0]+v[1]+v[2]+v[3];
  #pragma unroll
  for (int o = 16; o; o >>= 1) s += __shfl_xor_sync(0xffffffffu, s, o);
  float mu = s * (1.0f/128.0f);
  float q = 0.f;
  #pragma unroll
  for (int c = 0; c < 4; c++){ float t = v[c]-mu; q += t*t; }
  #pragma unroll
  for (int o = 16; o; o >>= 1) q += __shfl_xor_sync(0xffffffffu, q, o);
  float rstd = rsqrtf(q*(1.0f/128.0f) + 1e-5f);
  #pragma unroll
  for (int c = 0; c < 4; c++){
    int dd = lane*4 + c;
    float y = (v[c]-mu)*rstd*gamma[dd] + beta[dd];
    y = y > 0.f ? y : 0.f;
    out[(size_t)n*128 + dd] = X[(size_t)n*128 + dd] + y;
  }
}

// ---------------- launch ----------------
extern "C" void kernel_launch(void* const* d_in, const int* in_sizes, int n_in,
                              void* d_out, int out_size) {
  const float* prototypes = (const float*)d_in[0];
  // d_in[1] = labels (unused in forward)
  const float* W       = (const float*)d_in[2];
  const float* att_src = (const float*)d_in[3];
  const float* att_dst = (const float*)d_in[4];
  const float* bias    = (const float*)d_in[5];
  const float* gamma   = (const float*)d_in[6];
  const float* beta    = (const float*)d_in[7];
  float* out = (float*)d_out;

  cudaFuncSetAttribute(k_filter, cudaFuncAttributeMaxDynamicSharedMemorySize, SM_TOT);

  k_sqnorm<<<NN/8, 256>>>((const float4*)prototypes);
  k_tobf16<<<(NN*DD/2)/256, 256>>>(prototypes);
  k_filter<<<128, 256, SM_TOT>>>();
  k_rescore<<<NN/8, 256>>>(prototypes);
  k_xp<<<128, 256>>>(prototypes, W);
  k_attn<<<NN/8, 256>>>(att_src, att_dst);
  k_esum<<<(NE*2+255)/256, 256>>>();
  k_agg<<<(NE*2*32+255)/256, 256>>>();
  k_final<<<NN/8, 256>>>(prototypes, bias, gamma, beta, out);
}